// round 9
// baseline (speedup 1.0000x reference)
#include <cuda_runtime.h>
#include <cuda_fp16.h>
#include <cstdint>

#define B_ 64
#define N_ 512
#define H_ 1024
#define E_ 4
#define BN_EPS 1e-5f

// GEMM tile config: CTA 128x128, 4 warps of 64x64, BK=32, 4-stage cp.async, 3 CTAs/SM
#define BM 128
#define BNG 128
#define BKK 32
#define GT 128
#define STAGES 4
#define STAGE_BYTES 16384   // A 8K | B 8K
#define OFF_BH 8192
#define SMEM_BYTES (STAGES * STAGE_BYTES)

// ---------------- scratch (static device globals; no allocation) ----------------
__device__ __align__(256) __half g_xh[(size_t)B_ * N_ * H_];
__device__ __align__(256) __half g_adjh[(size_t)B_ * N_ * N_];
__device__ __align__(256) __half g_wh[(size_t)E_ * H_ * H_];
__device__ __align__(256) __half g_suph[(size_t)B_ * N_ * H_];
__device__ __align__(256) __half g_outh[(size_t)B_ * N_ * H_];
__device__ __align__(256) float g_mean_part[B_ * 8 * H_];
__device__ __align__(256) float g_sum[E_ * H_];
__device__ __align__(256) float g_ss[E_ * H_];
__device__ __align__(256) float g_scale[E_ * H_];
__device__ __align__(256) float g_shift[E_ * H_];
__device__ int g_top1[B_];

// ---------------- PTX helpers (base-family ISA) ----------------
__device__ __forceinline__ uint32_t smem_u32(const void* p) {
    uint32_t a;
    asm("{ .reg .u64 t; cvta.to.shared.u64 t, %1; cvt.u32.u64 %0, t; }" : "=r"(a) : "l"(p));
    return a;
}
__device__ __forceinline__ void cp16(uint32_t d, const void* g) {
    asm volatile("cp.async.cg.shared.global [%0], [%1], 16;" :: "r"(d), "l"(g));
}
__device__ __forceinline__ void ldsm_x4(uint32_t (&r)[4], uint32_t addr) {
    asm volatile("ldmatrix.sync.aligned.m8n8.x4.shared.b16 {%0,%1,%2,%3}, [%4];"
        : "=r"(r[0]), "=r"(r[1]), "=r"(r[2]), "=r"(r[3]) : "r"(addr));
}
__device__ __forceinline__ void ldsm_x4_t(uint32_t (&r)[4], uint32_t addr) {
    asm volatile("ldmatrix.sync.aligned.m8n8.x4.trans.shared.b16 {%0,%1,%2,%3}, [%4];"
        : "=r"(r[0]), "=r"(r[1]), "=r"(r[2]), "=r"(r[3]) : "r"(addr));
}
__device__ __forceinline__ void mma_f16(float (&c)[4], const uint32_t (&a)[4], const uint32_t* b) {
    asm volatile(
        "mma.sync.aligned.m16n8k16.row.col.f32.f16.f16.f32 "
        "{%0,%1,%2,%3}, {%4,%5,%6,%7}, {%8,%9}, {%0,%1,%2,%3};"
        : "+f"(c[0]), "+f"(c[1]), "+f"(c[2]), "+f"(c[3])
        : "r"(a[0]), "r"(a[1]), "r"(a[2]), "r"(a[3]), "r"(b[0]), "r"(b[1]));
}

// ---------------- k0: zero accumulators ----------
__global__ void zero_stats_kernel() {
    int i = blockIdx.x * blockDim.x + threadIdx.x;
    if (i < E_ * H_) { g_sum[i] = 0.f; g_ss[i] = 0.f; }
}

// ---------------- k1: partial column means + x -> fp16 convert (fused) ----------
__global__ void mean_cvt_kernel(const float* __restrict__ x) {
    int b = blockIdx.x, s = blockIdx.y;
    size_t base = (size_t)b * N_ * H_ + (size_t)s * 64 * H_;
    const float* xb = x + base;
    __half* xh = g_xh + base;
    for (int h = threadIdx.x; h < H_; h += blockDim.x) {
        float acc = 0.f;
        #pragma unroll 8
        for (int n = 0; n < 64; n++) {
            float v = xb[(size_t)n * H_ + h];
            xh[(size_t)n * H_ + h] = __float2half_rn(v);
            acc += v;
        }
        g_mean_part[(b * 8 + s) * H_ + h] = acc;
    }
}

// ---------------- k2: router + argmax ----------
__global__ void router_kernel(const float* __restrict__ rw, const float* __restrict__ rb) {
    int b = blockIdx.x;
    __shared__ float sred[E_][256];
    float acc[E_] = {0.f, 0.f, 0.f, 0.f};
    for (int h = threadIdx.x; h < H_; h += 256) {
        float m = 0.f;
        #pragma unroll
        for (int s = 0; s < 8; s++) m += g_mean_part[(b * 8 + s) * H_ + h];
        m *= (1.0f / (float)N_);
        #pragma unroll
        for (int e = 0; e < E_; e++) acc[e] += m * rw[h * E_ + e];
    }
    #pragma unroll
    for (int e = 0; e < E_; e++) sred[e][threadIdx.x] = acc[e];
    __syncthreads();
    for (int off = 128; off > 0; off >>= 1) {
        if (threadIdx.x < off) {
            #pragma unroll
            for (int e = 0; e < E_; e++) sred[e][threadIdx.x] += sred[e][threadIdx.x + off];
        }
        __syncthreads();
    }
    if (threadIdx.x == 0) {
        int best = 0;
        float bv = sred[0][0] + rb[0];
        for (int e = 1; e < E_; e++) {
            float v = sred[e][0] + rb[e];
            if (v > bv) { bv = v; best = e; }
        }
        g_top1[b] = best;
    }
}

// ---------------- k3: adj -> fp16 ----------
__global__ void cvt_adj_kernel(const float* __restrict__ src) {
    size_t i = ((size_t)blockIdx.x * blockDim.x + threadIdx.x) * 4;
    float4 v = *(const float4*)(src + i);
    *(__half2*)(g_adjh + i) = __floats2half2_rn(v.x, v.y);
    *(__half2*)(g_adjh + i + 2) = __floats2half2_rn(v.z, v.w);
}

// ---------------- k4: expert_w -> fp16 ----------
__global__ void cvt_w_kernel(const float* __restrict__ src) {
    size_t i = ((size_t)blockIdx.x * blockDim.x + threadIdx.x) * 4;
    float4 v = *(const float4*)(src + i);
    *(__half2*)(g_wh + i) = __floats2half2_rn(v.x, v.y);
    *(__half2*)(g_wh + i + 2) = __floats2half2_rn(v.z, v.w);
}

// ---------------- batched fp16 single-pass mma GEMM, 128-thread CTA, 3 CTAs/SM ----------------
// fp16 output; withStats adds fused per-expert BN statistics
__global__ __launch_bounds__(GT, 3)
void gemm_f16_kernel(const __half* __restrict__ Abase, long strideA, int lda,
                     const __half* __restrict__ Bbase, long strideB, int ldb, int useTop1,
                     __half* __restrict__ Ch, int withStats,
                     long strideC, int ldc, int K) {
    extern __shared__ __align__(128) char smem[];
    const uint32_t sb = smem_u32(smem);
    const int tid = threadIdx.x;
    const int lane = tid & 31, wid = tid >> 5;
    const int bz = blockIdx.z;
    const int m0 = blockIdx.y * BM, n0 = blockIdx.x * BNG;
    const int wm = (wid >> 1) * 64, wn = (wid & 1) * 64;

    const __half* A = Abase + (long)bz * strideA;
    const int sel = useTop1 ? g_top1[bz] : bz;
    const __half* Bg = Bbase + (long)sel * strideB;

    // cp.async roles: A 128 rows x 64B (1 row/thread); B 32 rows x 256B (4 chunks/thread)
    const int ar = tid;
    const int bk = tid >> 2, bn0 = (tid & 3) * 4;
    uint32_t a_off[4], b_off[4];
    #pragma unroll
    for (int q = 0; q < 4; q++)
        a_off[q] = (uint32_t)(ar * 64 + ((q ^ ((ar >> 1) & 3)) << 4));
    #pragma unroll
    for (int q = 0; q < 4; q++) {
        int nc = bn0 + q;
        b_off[q] = (uint32_t)(bk * 256 + ((nc ^ (bk & 7)) << 4));
    }
    const __half* a_g = A + (long)(m0 + ar) * lda;
    const __half* b_g = Bg + (long)bk * ldb + n0 + bn0 * 8;

    float acc[4][8][4];
    #pragma unroll
    for (int a = 0; a < 4; a++)
        #pragma unroll
        for (int b2 = 0; b2 < 8; b2++)
            #pragma unroll
            for (int c = 0; c < 4; c++) acc[a][b2][c] = 0.f;

    auto issue = [&](int i) {
        uint32_t st = sb + (uint32_t)((i & (STAGES - 1)) * STAGE_BYTES);
        const __half* ag = a_g + (long)i * BKK;
        #pragma unroll
        for (int q = 0; q < 4; q++) cp16(st + a_off[q], ag + q * 8);
        const __half* bg = b_g + (long)i * BKK * ldb;
        #pragma unroll
        for (int q = 0; q < 4; q++) cp16(st + OFF_BH + b_off[q], bg + q * 8);
        asm volatile("cp.async.commit_group;" ::: "memory");
    };

    auto mma_tile = [&](int s) {
        const uint32_t aB = sb + (uint32_t)(s * STAGE_BYTES);
        #pragma unroll
        for (int ks = 0; ks < 2; ks++) {
            uint32_t ahf[4][4];
            #pragma unroll
            for (int mt = 0; mt < 4; mt++) {
                int r = wm + mt * 16 + (lane & 15);
                int c = ks * 2 + (lane >> 4);
                ldsm_x4(ahf[mt], aB + (uint32_t)(r * 64 + ((c ^ ((r >> 1) & 3)) << 4)));
            }
            int k = ks * 16 + (lane & 15);
            #pragma unroll
            for (int nt = 0; nt < 4; nt++) {
                int nl = wn + nt * 16 + ((lane >> 4) << 3);
                uint32_t boff = (uint32_t)(k * 256 + (((nl >> 3) ^ (k & 7)) << 4));
                uint32_t r4[4];
                ldsm_x4_t(r4, aB + OFF_BH + boff);
                #pragma unroll
                for (int mt = 0; mt < 4; mt++) {
                    mma_f16(acc[mt][nt * 2], ahf[mt], r4);
                    mma_f16(acc[mt][nt * 2 + 1], ahf[mt], r4 + 2);
                }
            }
        }
    };

    const int nk = K / BKK;
    issue(0); issue(1); issue(2);
    for (int i = 0; i < nk; i++) {
        asm volatile("cp.async.wait_group 2;" ::: "memory");
        __syncthreads();
        mma_tile(i & (STAGES - 1));
        if (i + 3 < nk) issue(i + 3);
        else asm volatile("cp.async.commit_group;" ::: "memory");
    }

    // epilogue: fp16 output
    __half* CH = Ch + (long)bz * strideC;
    #pragma unroll
    for (int mt = 0; mt < 4; mt++) {
        int row0 = m0 + wm + mt * 16 + (lane >> 2);
        #pragma unroll
        for (int n8 = 0; n8 < 8; n8++) {
            int col = n0 + wn + n8 * 8 + (lane & 3) * 2;
            *(__half2*)(CH + (long)row0 * ldc + col) =
                __floats2half2_rn(acc[mt][n8][0], acc[mt][n8][1]);
            *(__half2*)(CH + (long)(row0 + 8) * ldc + col) =
                __floats2half2_rn(acc[mt][n8][2], acc[mt][n8][3]);
        }
    }
    if (withStats) {
        int e = g_top1[bz];
        #pragma unroll
        for (int n8 = 0; n8 < 8; n8++) {
            #pragma unroll
            for (int c2 = 0; c2 < 2; c2++) {
                float s = 0.f, q = 0.f;
                #pragma unroll
                for (int mt = 0; mt < 4; mt++) {
                    float v0 = acc[mt][n8][c2], v1 = acc[mt][n8][c2 + 2];
                    s += v0 + v1;
                    q += v0 * v0 + v1 * v1;
                }
                s += __shfl_xor_sync(0xFFFFFFFFu, s, 4);
                q += __shfl_xor_sync(0xFFFFFFFFu, q, 4);
                s += __shfl_xor_sync(0xFFFFFFFFu, s, 8);
                q += __shfl_xor_sync(0xFFFFFFFFu, q, 8);
                s += __shfl_xor_sync(0xFFFFFFFFu, s, 16);
                q += __shfl_xor_sync(0xFFFFFFFFu, q, 16);
                if ((lane >> 2) == 0) {
                    int col = n0 + wn + n8 * 8 + (lane & 3) * 2 + c2;
                    atomicAdd(&g_sum[e * H_ + col], s);
                    atomicAdd(&g_ss[e * H_ + col], q);
                }
            }
        }
    }
}

// ---------------- k6: finalize BN scale/shift ----------
__global__ void finalize_kernel(const float* __restrict__ gamma, const float* __restrict__ beta) {
    int e = blockIdx.x, h = threadIdx.x;
    int cg = 0;
    for (int b = 0; b < B_; b++) cg += (g_top1[b] == e);
    float cnt = fmaxf((float)cg * (float)N_, 1.0f);
    float mean = g_sum[e * H_ + h] / cnt;
    float var = g_ss[e * H_ + h] / cnt - mean * mean;
    float inv = rsqrtf(var + BN_EPS);
    float sc = gamma[e * H_ + h] * inv;
    g_scale[e * H_ + h] = sc;
    g_shift[e * H_ + h] = beta[e * H_ + h] - mean * sc;
}

// ---------------- k7: apply BN + ReLU (fp16 in, fp32 out) ----------
__global__ void bn_relu_kernel(float* __restrict__ out) {
    size_t idx = ((size_t)blockIdx.x * blockDim.x + threadIdx.x) * 4;
    int b = (int)(idx / ((size_t)N_ * H_));
    int h = (int)(idx % H_);
    int e = g_top1[b];
    __half2 i0 = *(const __half2*)(g_outh + idx);
    __half2 i1 = *(const __half2*)(g_outh + idx + 2);
    float4 v = make_float4(__half2float(i0.x), __half2float(i0.y),
                           __half2float(i1.x), __half2float(i1.y));
    float4 sc = *(const float4*)&g_scale[e * H_ + h];
    float4 sh = *(const float4*)&g_shift[e * H_ + h];
    v.x = fmaxf(v.x * sc.x + sh.x, 0.f);
    v.y = fmaxf(v.y * sc.y + sh.y, 0.f);
    v.z = fmaxf(v.z * sc.z + sh.z, 0.f);
    v.w = fmaxf(v.w * sc.w + sh.w, 0.f);
    *(float4*)(out + idx) = v;
}

// ---------------- launcher (single stream, serial) ----------------
extern "C" void kernel_launch(void* const* d_in, const int* in_sizes, int n_in,
                              void* d_out, int out_size) {
    (void)in_sizes; (void)n_in; (void)out_size;
    const float* x        = (const float*)d_in[0];   // [B,N,H]
    const float* adj      = (const float*)d_in[1];   // [B,N,N]
    const float* router_w = (const float*)d_in[2];   // [H,E]
    const float* router_b = (const float*)d_in[3];   // [E]
    const float* expert_w = (const float*)d_in[4];   // [E,H,H]
    const float* bn_gamma = (const float*)d_in[5];   // [E,H]
    const float* bn_beta  = (const float*)d_in[6];   // [E,H]
    float* out = (float*)d_out;                      // [B,N,H]

    __half *xh, *adjh, *wh, *suph, *outh;
    cudaGetSymbolAddress((void**)&xh, g_xh);
    cudaGetSymbolAddress((void**)&adjh, g_adjh);
    cudaGetSymbolAddress((void**)&wh, g_wh);
    cudaGetSymbolAddress((void**)&suph, g_suph);
    cudaGetSymbolAddress((void**)&outh, g_outh);

    cudaFuncSetAttribute(gemm_f16_kernel, cudaFuncAttributeMaxDynamicSharedMemorySize, SMEM_BYTES);

    zero_stats_kernel<<<16, 256>>>();
    mean_cvt_kernel<<<dim3(B_, 8), 256>>>(x);
    router_kernel<<<B_, 256>>>(router_w, router_b);
    cvt_adj_kernel<<<(unsigned)((size_t)B_ * N_ * N_ / 4 / 256), 256>>>(adj);
    cvt_w_kernel<<<(unsigned)((size_t)E_ * H_ * H_ / 4 / 256), 256>>>(expert_w);

    // support[b] = x[b] @ expert_w[top1[b]]  -> fp16
    gemm_f16_kernel<<<dim3(H_ / BNG, N_ / BM, B_), GT, SMEM_BYTES>>>(
        xh, (long)N_ * H_, H_,
        wh, (long)H_ * H_, H_, 1,
        suph, 0, (long)N_ * H_, H_, H_);

    // outh[b] = adj[b] @ support[b]  -> fp16 + fused stats
    gemm_f16_kernel<<<dim3(H_ / BNG, N_ / BM, B_), GT, SMEM_BYTES>>>(
        adjh, (long)N_ * N_, N_,
        suph, (long)N_ * H_, H_, 0,
        outh, 1, (long)N_ * H_, H_, N_);

    finalize_kernel<<<E_, H_>>>(bn_gamma, bn_beta);

    size_t total4 = (size_t)B_ * N_ * H_ / 4;
    bn_relu_kernel<<<(unsigned)(total4 / 256), 256>>>(out);
}

// round 10
// speedup vs baseline: 1.1215x; 1.1215x over previous
#include <cuda_runtime.h>
#include <cuda_fp16.h>
#include <cstdint>

#define B_ 64
#define N_ 512
#define H_ 1024
#define E_ 4
#define BN_EPS 1e-5f

// GEMM tile config: CTA 128x256, 8 warps of 64x64, BK=32, 6-stage cp.async
#define BM 128
#define BNG 256
#define BKK 32
#define GT 256
#define STAGES 6
#define STAGE_BYTES 24576   // A 8K | B 16K
#define OFF_BH 8192
#define SMEM_BYTES (STAGES * STAGE_BYTES)

// ---------------- scratch (static device globals; no allocation) ----------------
__device__ __align__(256) __half g_xh[(size_t)B_ * N_ * H_];
__device__ __align__(256) __half g_adjh[(size_t)B_ * N_ * N_];
__device__ __align__(256) __half g_wh[(size_t)E_ * H_ * H_];
__device__ __align__(256) __half g_suph[(size_t)B_ * N_ * H_];
__device__ __align__(256) __half g_outh[(size_t)B_ * N_ * H_];
__device__ __align__(256) float g_mean_part[B_ * 8 * H_];
__device__ __align__(256) float g_sum[E_ * H_];
__device__ __align__(256) float g_ss[E_ * H_];
__device__ __align__(256) float g_scale[E_ * H_];
__device__ __align__(256) float g_shift[E_ * H_];
__device__ int g_top1[B_];

// ---------------- PTX helpers (base-family ISA) ----------------
__device__ __forceinline__ uint32_t smem_u32(const void* p) {
    uint32_t a;
    asm("{ .reg .u64 t; cvta.to.shared.u64 t, %1; cvt.u32.u64 %0, t; }" : "=r"(a) : "l"(p));
    return a;
}
__device__ __forceinline__ void cp16(uint32_t d, const void* g) {
    asm volatile("cp.async.cg.shared.global [%0], [%1], 16;" :: "r"(d), "l"(g));
}
__device__ __forceinline__ void ldsm_x4(uint32_t (&r)[4], uint32_t addr) {
    asm volatile("ldmatrix.sync.aligned.m8n8.x4.shared.b16 {%0,%1,%2,%3}, [%4];"
        : "=r"(r[0]), "=r"(r[1]), "=r"(r[2]), "=r"(r[3]) : "r"(addr));
}
__device__ __forceinline__ void ldsm_x4_t(uint32_t (&r)[4], uint32_t addr) {
    asm volatile("ldmatrix.sync.aligned.m8n8.x4.trans.shared.b16 {%0,%1,%2,%3}, [%4];"
        : "=r"(r[0]), "=r"(r[1]), "=r"(r[2]), "=r"(r[3]) : "r"(addr));
}
__device__ __forceinline__ void mma_f16(float (&c)[4], const uint32_t (&a)[4], const uint32_t* b) {
    asm volatile(
        "mma.sync.aligned.m16n8k16.row.col.f32.f16.f16.f32 "
        "{%0,%1,%2,%3}, {%4,%5,%6,%7}, {%8,%9}, {%0,%1,%2,%3};"
        : "+f"(c[0]), "+f"(c[1]), "+f"(c[2]), "+f"(c[3])
        : "r"(a[0]), "r"(a[1]), "r"(a[2]), "r"(a[3]), "r"(b[0]), "r"(b[1]));
}

// ---------------- k0: zero accumulators ----------
__global__ void zero_stats_kernel() {
    int i = blockIdx.x * blockDim.x + threadIdx.x;
    if (i < E_ * H_) { g_sum[i] = 0.f; g_ss[i] = 0.f; }
}

// ---------------- k1: partial column means + x -> fp16 convert (fused) ----------
__global__ void mean_cvt_kernel(const float* __restrict__ x) {
    int b = blockIdx.x, s = blockIdx.y;
    size_t base = (size_t)b * N_ * H_ + (size_t)s * 64 * H_;
    const float* xb = x + base;
    __half* xh = g_xh + base;
    for (int h = threadIdx.x; h < H_; h += blockDim.x) {
        float acc = 0.f;
        #pragma unroll 8
        for (int n = 0; n < 64; n++) {
            float v = xb[(size_t)n * H_ + h];
            xh[(size_t)n * H_ + h] = __float2half_rn(v);
            acc += v;
        }
        g_mean_part[(b * 8 + s) * H_ + h] = acc;
    }
}

// ---------------- k2: router + argmax ----------
__global__ void router_kernel(const float* __restrict__ rw, const float* __restrict__ rb) {
    int b = blockIdx.x;
    __shared__ float sred[E_][256];
    float acc[E_] = {0.f, 0.f, 0.f, 0.f};
    for (int h = threadIdx.x; h < H_; h += 256) {
        float m = 0.f;
        #pragma unroll
        for (int s = 0; s < 8; s++) m += g_mean_part[(b * 8 + s) * H_ + h];
        m *= (1.0f / (float)N_);
        #pragma unroll
        for (int e = 0; e < E_; e++) acc[e] += m * rw[h * E_ + e];
    }
    #pragma unroll
    for (int e = 0; e < E_; e++) sred[e][threadIdx.x] = acc[e];
    __syncthreads();
    for (int off = 128; off > 0; off >>= 1) {
        if (threadIdx.x < off) {
            #pragma unroll
            for (int e = 0; e < E_; e++) sred[e][threadIdx.x] += sred[e][threadIdx.x + off];
        }
        __syncthreads();
    }
    if (threadIdx.x == 0) {
        int best = 0;
        float bv = sred[0][0] + rb[0];
        for (int e = 1; e < E_; e++) {
            float v = sred[e][0] + rb[e];
            if (v > bv) { bv = v; best = e; }
        }
        g_top1[b] = best;
    }
}

// ---------------- k3: adj -> fp16 ----------
__global__ void cvt_adj_kernel(const float* __restrict__ src) {
    size_t i = ((size_t)blockIdx.x * blockDim.x + threadIdx.x) * 4;
    float4 v = *(const float4*)(src + i);
    *(__half2*)(g_adjh + i) = __floats2half2_rn(v.x, v.y);
    *(__half2*)(g_adjh + i + 2) = __floats2half2_rn(v.z, v.w);
}

// ---------------- k4: expert_w -> fp16 ----------
__global__ void cvt_w_kernel(const float* __restrict__ src) {
    size_t i = ((size_t)blockIdx.x * blockDim.x + threadIdx.x) * 4;
    float4 v = *(const float4*)(src + i);
    *(__half2*)(g_wh + i) = __floats2half2_rn(v.x, v.y);
    *(__half2*)(g_wh + i + 2) = __floats2half2_rn(v.z, v.w);
}

// ---------------- batched fp16 single-pass mma GEMM (R7 + deeper pipeline) ----------------
// fp16 output; withStats adds fused per-expert BN statistics
__global__ __launch_bounds__(GT, 1)
void gemm_f16_kernel(const __half* __restrict__ Abase, long strideA, int lda,
                     const __half* __restrict__ Bbase, long strideB, int ldb, int useTop1,
                     __half* __restrict__ Ch, int withStats,
                     long strideC, int ldc, int K) {
    extern __shared__ __align__(128) char smem[];
    const uint32_t sb = smem_u32(smem);
    const int tid = threadIdx.x;
    const int lane = tid & 31, wid = tid >> 5;
    const int bz = blockIdx.z;
    const int m0 = blockIdx.y * BM, n0 = blockIdx.x * BNG;
    const int wm = (wid >> 2) * 64, wn = (wid & 3) * 64;

    const __half* A = Abase + (long)bz * strideA;
    const int sel = useTop1 ? g_top1[bz] : bz;
    const __half* Bg = Bbase + (long)sel * strideB;

    // cp.async roles
    const int ar = tid >> 1, ac0 = (tid & 1) * 2;      // A: row, chunk pair
    const int bk = tid >> 3, bn0 = (tid & 7) * 4;      // B: k row, chunk quad
    uint32_t a_off[2], b_off[4];
    #pragma unroll
    for (int q = 0; q < 2; q++) {
        int c = ac0 + q;
        a_off[q] = (uint32_t)(ar * 64 + ((c ^ ((ar >> 1) & 3)) << 4));
    }
    #pragma unroll
    for (int q = 0; q < 4; q++) {
        int nc = bn0 + q;
        b_off[q] = (uint32_t)((nc >> 4) * 8192 + bk * 256 + (((nc & 15) ^ (bk & 7)) << 4));
    }
    const __half* a_g = A + (long)(m0 + ar) * lda + ac0 * 8;
    const __half* b_g = Bg + (long)bk * ldb + n0 + bn0 * 8;

    float acc[4][8][4];
    #pragma unroll
    for (int a = 0; a < 4; a++)
        #pragma unroll
        for (int b2 = 0; b2 < 8; b2++)
            #pragma unroll
            for (int c = 0; c < 4; c++) acc[a][b2][c] = 0.f;

    auto issue = [&](int i) {
        uint32_t st = sb + (uint32_t)((i % STAGES) * STAGE_BYTES);
        const __half* ag = a_g + (long)i * BKK;
        #pragma unroll
        for (int q = 0; q < 2; q++) cp16(st + a_off[q], ag + q * 8);
        const __half* bg = b_g + (long)i * BKK * ldb;
        #pragma unroll
        for (int q = 0; q < 4; q++) cp16(st + OFF_BH + b_off[q], bg + q * 8);
        asm volatile("cp.async.commit_group;" ::: "memory");
    };

    auto mma_tile = [&](int s) {
        const uint32_t aB = sb + (uint32_t)(s * STAGE_BYTES);
        #pragma unroll
        for (int ks = 0; ks < 2; ks++) {
            uint32_t ahf[4][4];
            #pragma unroll
            for (int mt = 0; mt < 4; mt++) {
                int r = wm + mt * 16 + (lane & 15);
                int c = ks * 2 + (lane >> 4);
                ldsm_x4(ahf[mt], aB + (uint32_t)(r * 64 + ((c ^ ((r >> 1) & 3)) << 4)));
            }
            int k = ks * 16 + (lane & 15);
            #pragma unroll
            for (int nt = 0; nt < 4; nt++) {
                int nl = wn + nt * 16 + ((lane >> 4) << 3);
                uint32_t boff = (uint32_t)((nl >> 7) * 8192 + k * 256 +
                                           ((((nl & 127) >> 3) ^ (k & 7)) << 4));
                uint32_t r4[4];
                ldsm_x4_t(r4, aB + OFF_BH + boff);
                #pragma unroll
                for (int mt = 0; mt < 4; mt++) {
                    mma_f16(acc[mt][nt * 2], ahf[mt], r4);
                    mma_f16(acc[mt][nt * 2 + 1], ahf[mt], r4 + 2);
                }
            }
        }
    };

    const int nk = K / BKK;
    issue(0); issue(1); issue(2); issue(3); issue(4);
    for (int i = 0; i < nk; i++) {
        asm volatile("cp.async.wait_group 4;" ::: "memory");
        __syncthreads();
        mma_tile(i % STAGES);
        if (i + 5 < nk) issue(i + 5);
        else asm volatile("cp.async.commit_group;" ::: "memory");
    }

    // epilogue: fp16 output
    __half* CH = Ch + (long)bz * strideC;
    #pragma unroll
    for (int mt = 0; mt < 4; mt++) {
        int row0 = m0 + wm + mt * 16 + (lane >> 2);
        #pragma unroll
        for (int n8 = 0; n8 < 8; n8++) {
            int col = n0 + wn + n8 * 8 + (lane & 3) * 2;
            *(__half2*)(CH + (long)row0 * ldc + col) =
                __floats2half2_rn(acc[mt][n8][0], acc[mt][n8][1]);
            *(__half2*)(CH + (long)(row0 + 8) * ldc + col) =
                __floats2half2_rn(acc[mt][n8][2], acc[mt][n8][3]);
        }
    }
    if (withStats) {
        int e = g_top1[bz];
        #pragma unroll
        for (int n8 = 0; n8 < 8; n8++) {
            #pragma unroll
            for (int c2 = 0; c2 < 2; c2++) {
                float s = 0.f, q = 0.f;
                #pragma unroll
                for (int mt = 0; mt < 4; mt++) {
                    float v0 = acc[mt][n8][c2], v1 = acc[mt][n8][c2 + 2];
                    s += v0 + v1;
                    q += v0 * v0 + v1 * v1;
                }
                s += __shfl_xor_sync(0xFFFFFFFFu, s, 4);
                q += __shfl_xor_sync(0xFFFFFFFFu, q, 4);
                s += __shfl_xor_sync(0xFFFFFFFFu, s, 8);
                q += __shfl_xor_sync(0xFFFFFFFFu, q, 8);
                s += __shfl_xor_sync(0xFFFFFFFFu, s, 16);
                q += __shfl_xor_sync(0xFFFFFFFFu, q, 16);
                if ((lane >> 2) == 0) {
                    int col = n0 + wn + n8 * 8 + (lane & 3) * 2 + c2;
                    atomicAdd(&g_sum[e * H_ + col], s);
                    atomicAdd(&g_ss[e * H_ + col], q);
                }
            }
        }
    }
}

// ---------------- k6: finalize BN scale/shift ----------
__global__ void finalize_kernel(const float* __restrict__ gamma, const float* __restrict__ beta) {
    int e = blockIdx.x, h = threadIdx.x;
    int cg = 0;
    for (int b = 0; b < B_; b++) cg += (g_top1[b] == e);
    float cnt = fmaxf((float)cg * (float)N_, 1.0f);
    float mean = g_sum[e * H_ + h] / cnt;
    float var = g_ss[e * H_ + h] / cnt - mean * mean;
    float inv = rsqrtf(var + BN_EPS);
    float sc = gamma[e * H_ + h] * inv;
    g_scale[e * H_ + h] = sc;
    g_shift[e * H_ + h] = beta[e * H_ + h] - mean * sc;
}

// ---------------- k7: apply BN + ReLU (fp16 in, fp32 out) ----------
__global__ void bn_relu_kernel(float* __restrict__ out) {
    size_t idx = ((size_t)blockIdx.x * blockDim.x + threadIdx.x) * 4;
    int b = (int)(idx / ((size_t)N_ * H_));
    int h = (int)(idx % H_);
    int e = g_top1[b];
    __half2 i0 = *(const __half2*)(g_outh + idx);
    __half2 i1 = *(const __half2*)(g_outh + idx + 2);
    float4 v = make_float4(__half2float(i0.x), __half2float(i0.y),
                           __half2float(i1.x), __half2float(i1.y));
    float4 sc = *(const float4*)&g_scale[e * H_ + h];
    float4 sh = *(const float4*)&g_shift[e * H_ + h];
    v.x = fmaxf(v.x * sc.x + sh.x, 0.f);
    v.y = fmaxf(v.y * sc.y + sh.y, 0.f);
    v.z = fmaxf(v.z * sc.z + sh.z, 0.f);
    v.w = fmaxf(v.w * sc.w + sh.w, 0.f);
    *(float4*)(out + idx) = v;
}

// ---------------- launcher (single stream, serial; R7 ordering) ----------------
extern "C" void kernel_launch(void* const* d_in, const int* in_sizes, int n_in,
                              void* d_out, int out_size) {
    (void)in_sizes; (void)n_in; (void)out_size;
    const float* x        = (const float*)d_in[0];   // [B,N,H]
    const float* adj      = (const float*)d_in[1];   // [B,N,N]
    const float* router_w = (const float*)d_in[2];   // [H,E]
    const float* router_b = (const float*)d_in[3];   // [E]
    const float* expert_w = (const float*)d_in[4];   // [E,H,H]
    const float* bn_gamma = (const float*)d_in[5];   // [E,H]
    const float* bn_beta  = (const float*)d_in[6];   // [E,H]
    float* out = (float*)d_out;                      // [B,N,H]

    __half *xh, *adjh, *wh, *suph, *outh;
    cudaGetSymbolAddress((void**)&xh, g_xh);
    cudaGetSymbolAddress((void**)&adjh, g_adjh);
    cudaGetSymbolAddress((void**)&wh, g_wh);
    cudaGetSymbolAddress((void**)&suph, g_suph);
    cudaGetSymbolAddress((void**)&outh, g_outh);

    cudaFuncSetAttribute(gemm_f16_kernel, cudaFuncAttributeMaxDynamicSharedMemorySize, SMEM_BYTES);

    zero_stats_kernel<<<16, 256>>>();
    mean_cvt_kernel<<<dim3(B_, 8), 256>>>(x);
    router_kernel<<<B_, 256>>>(router_w, router_b);
    cvt_adj_kernel<<<(unsigned)((size_t)B_ * N_ * N_ / 4 / 256), 256>>>(adj);
    cvt_w_kernel<<<(unsigned)((size_t)E_ * H_ * H_ / 4 / 256), 256>>>(expert_w);

    // support[b] = x[b] @ expert_w[top1[b]]  -> fp16
    gemm_f16_kernel<<<dim3(H_ / BNG, N_ / BM, B_), GT, SMEM_BYTES>>>(
        xh, (long)N_ * H_, H_,
        wh, (long)H_ * H_, H_, 1,
        suph, 0, (long)N_ * H_, H_, H_);

    // outh[b] = adj[b] @ support[b]  -> fp16 + fused stats
    gemm_f16_kernel<<<dim3(H_ / BNG, N_ / BM, B_), GT, SMEM_BYTES>>>(
        adjh, (long)N_ * N_, N_,
        suph, (long)N_ * H_, H_, 0,
        outh, 1, (long)N_ * H_, H_, N_);

    finalize_kernel<<<E_, H_>>>(bn_gamma, bn_beta);

    size_t total4 = (size_t)B_ * N_ * H_ / 4;
    bn_relu_kernel<<<(unsigned)(total4 / 256), 256>>>(out);
}

// round 11
// speedup vs baseline: 1.1393x; 1.0159x over previous
#include <cuda_runtime.h>
#include <cuda_fp16.h>
#include <cstdint>

#define B_ 64
#define N_ 512
#define H_ 1024
#define E_ 4
#define BN_EPS 1e-5f

// GEMM tile config: CTA 128x256, 8 warps of 64x64, BK=32, 4-stage cp.async, persistent
#define BM 128
#define BNG 256
#define BKK 32
#define GT 256
#define STAGES 4
#define STAGE_BYTES 24576   // A 8K | B 16K
#define OFF_BH 8192
#define SMEM_BYTES (STAGES * STAGE_BYTES)

// ---------------- scratch (static device globals; no allocation) ----------------
__device__ __align__(256) __half g_xh[(size_t)B_ * N_ * H_];
__device__ __align__(256) __half g_adjh[(size_t)B_ * N_ * N_];
__device__ __align__(256) __half g_wh[(size_t)E_ * H_ * H_];
__device__ __align__(256) __half g_suph[(size_t)B_ * N_ * H_];
__device__ __align__(256) __half g_outh[(size_t)B_ * N_ * H_];
__device__ __align__(256) float g_mean_part[B_ * 8 * H_];
__device__ __align__(256) float g_sum[E_ * H_];
__device__ __align__(256) float g_ss[E_ * H_];
__device__ __align__(256) float g_scale[E_ * H_];
__device__ __align__(256) float g_shift[E_ * H_];
__device__ int g_top1[B_];

// ---------------- PTX helpers (base-family ISA) ----------------
__device__ __forceinline__ uint32_t smem_u32(const void* p) {
    uint32_t a;
    asm("{ .reg .u64 t; cvta.to.shared.u64 t, %1; cvt.u32.u64 %0, t; }" : "=r"(a) : "l"(p));
    return a;
}
__device__ __forceinline__ void cp16(uint32_t d, const void* g) {
    asm volatile("cp.async.cg.shared.global [%0], [%1], 16;" :: "r"(d), "l"(g));
}
__device__ __forceinline__ void ldsm_x4(uint32_t (&r)[4], uint32_t addr) {
    asm volatile("ldmatrix.sync.aligned.m8n8.x4.shared.b16 {%0,%1,%2,%3}, [%4];"
        : "=r"(r[0]), "=r"(r[1]), "=r"(r[2]), "=r"(r[3]) : "r"(addr));
}
__device__ __forceinline__ void ldsm_x4_t(uint32_t (&r)[4], uint32_t addr) {
    asm volatile("ldmatrix.sync.aligned.m8n8.x4.trans.shared.b16 {%0,%1,%2,%3}, [%4];"
        : "=r"(r[0]), "=r"(r[1]), "=r"(r[2]), "=r"(r[3]) : "r"(addr));
}
__device__ __forceinline__ void mma_f16(float (&c)[4], const uint32_t (&a)[4], const uint32_t* b) {
    asm volatile(
        "mma.sync.aligned.m16n8k16.row.col.f32.f16.f16.f32 "
        "{%0,%1,%2,%3}, {%4,%5,%6,%7}, {%8,%9}, {%0,%1,%2,%3};"
        : "+f"(c[0]), "+f"(c[1]), "+f"(c[2]), "+f"(c[3])
        : "r"(a[0]), "r"(a[1]), "r"(a[2]), "r"(a[3]), "r"(b[0]), "r"(b[1]));
}

// ---------------- k1: partial column means + x -> fp16 convert (fused) ----------
__global__ void mean_cvt_kernel(const float* __restrict__ x) {
    int b = blockIdx.x, s = blockIdx.y;
    size_t base = (size_t)b * N_ * H_ + (size_t)s * 64 * H_;
    const float* xb = x + base;
    __half* xh = g_xh + base;
    for (int h = threadIdx.x; h < H_; h += blockDim.x) {
        float acc = 0.f;
        #pragma unroll 8
        for (int n = 0; n < 64; n++) {
            float v = xb[(size_t)n * H_ + h];
            xh[(size_t)n * H_ + h] = __float2half_rn(v);
            acc += v;
        }
        g_mean_part[(b * 8 + s) * H_ + h] = acc;
    }
}

// ---------------- k2: router + argmax ----------
__global__ void router_kernel(const float* __restrict__ rw, const float* __restrict__ rb) {
    int b = blockIdx.x;
    __shared__ float sred[E_][256];
    float acc[E_] = {0.f, 0.f, 0.f, 0.f};
    for (int h = threadIdx.x; h < H_; h += 256) {
        float m = 0.f;
        #pragma unroll
        for (int s = 0; s < 8; s++) m += g_mean_part[(b * 8 + s) * H_ + h];
        m *= (1.0f / (float)N_);
        #pragma unroll
        for (int e = 0; e < E_; e++) acc[e] += m * rw[h * E_ + e];
    }
    #pragma unroll
    for (int e = 0; e < E_; e++) sred[e][threadIdx.x] = acc[e];
    __syncthreads();
    for (int off = 128; off > 0; off >>= 1) {
        if (threadIdx.x < off) {
            #pragma unroll
            for (int e = 0; e < E_; e++) sred[e][threadIdx.x] += sred[e][threadIdx.x + off];
        }
        __syncthreads();
    }
    if (threadIdx.x == 0) {
        int best = 0;
        float bv = sred[0][0] + rb[0];
        for (int e = 1; e < E_; e++) {
            float v = sred[e][0] + rb[e];
            if (v > bv) { bv = v; best = e; }
        }
        g_top1[b] = best;
    }
}

// ---------------- k3: adj -> fp16 ----------
__global__ void cvt_adj_kernel(const float* __restrict__ src) {
    size_t i = ((size_t)blockIdx.x * blockDim.x + threadIdx.x) * 4;
    float4 v = *(const float4*)(src + i);
    *(__half2*)(g_adjh + i) = __floats2half2_rn(v.x, v.y);
    *(__half2*)(g_adjh + i + 2) = __floats2half2_rn(v.z, v.w);
}

// ---------------- k4: expert_w -> fp16  (+ fused stats zeroing) ----------
__global__ void cvt_w_kernel(const float* __restrict__ src) {
    size_t t = (size_t)blockIdx.x * blockDim.x + threadIdx.x;
    if (t < E_ * H_) { g_sum[t] = 0.f; g_ss[t] = 0.f; }
    size_t i = t * 4;
    float4 v = *(const float4*)(src + i);
    *(__half2*)(g_wh + i) = __floats2half2_rn(v.x, v.y);
    *(__half2*)(g_wh + i + 2) = __floats2half2_rn(v.z, v.w);
}

// ---------------- persistent batched fp16 mma GEMM (R7 pipeline per tile) ----------------
// fp16 output; withStats adds fused per-expert BN statistics
__global__ __launch_bounds__(GT, 1)
void gemm_f16_kernel(const __half* __restrict__ Abase, long strideA, int lda,
                     const __half* __restrict__ Bbase, long strideB, int ldb, int useTop1,
                     __half* __restrict__ Ch, int withStats,
                     long strideC, int ldc, int K, int nTilesN, int nTilesTotal) {
    extern __shared__ __align__(128) char smem[];
    const uint32_t sb = smem_u32(smem);
    const int tid = threadIdx.x;
    const int lane = tid & 31, wid = tid >> 5;
    const int wm = (wid >> 2) * 64, wn = (wid & 3) * 64;
    const int tilesPerB = nTilesN * (N_ / BM);

    // cp.async/smem role constants (tile-independent)
    const int ar = tid >> 1, ac0 = (tid & 1) * 2;
    const int bk = tid >> 3, bn0 = (tid & 7) * 4;
    uint32_t a_off[2], b_off[4];
    #pragma unroll
    for (int q = 0; q < 2; q++) {
        int c = ac0 + q;
        a_off[q] = (uint32_t)(ar * 64 + ((c ^ ((ar >> 1) & 3)) << 4));
    }
    #pragma unroll
    for (int q = 0; q < 4; q++) {
        int nc = bn0 + q;
        b_off[q] = (uint32_t)((nc >> 4) * 8192 + bk * 256 + (((nc & 15) ^ (bk & 7)) << 4));
    }

    const int nk = K / BKK;

    for (int t = blockIdx.x; t < nTilesTotal; t += gridDim.x) {
        const int bz = t / tilesPerB;
        const int r = t - bz * tilesPerB;
        const int n0 = (r % nTilesN) * BNG;
        const int m0 = (r / nTilesN) * BM;

        const __half* A = Abase + (long)bz * strideA;
        const int sel = useTop1 ? g_top1[bz] : bz;
        const __half* Bg = Bbase + (long)sel * strideB;
        const __half* a_g = A + (long)(m0 + ar) * lda + ac0 * 8;
        const __half* b_g = Bg + (long)bk * ldb + n0 + bn0 * 8;

        float acc[4][8][4];
        #pragma unroll
        for (int a = 0; a < 4; a++)
            #pragma unroll
            for (int b2 = 0; b2 < 8; b2++)
                #pragma unroll
                for (int c = 0; c < 4; c++) acc[a][b2][c] = 0.f;

        auto issue = [&](int i) {
            uint32_t st = sb + (uint32_t)((i & (STAGES - 1)) * STAGE_BYTES);
            const __half* ag = a_g + (long)i * BKK;
            #pragma unroll
            for (int q = 0; q < 2; q++) cp16(st + a_off[q], ag + q * 8);
            const __half* bg = b_g + (long)i * BKK * ldb;
            #pragma unroll
            for (int q = 0; q < 4; q++) cp16(st + OFF_BH + b_off[q], bg + q * 8);
            asm volatile("cp.async.commit_group;" ::: "memory");
        };

        auto mma_tile = [&](int s) {
            const uint32_t aB = sb + (uint32_t)(s * STAGE_BYTES);
            #pragma unroll
            for (int ks = 0; ks < 2; ks++) {
                uint32_t ahf[4][4];
                #pragma unroll
                for (int mt = 0; mt < 4; mt++) {
                    int rr = wm + mt * 16 + (lane & 15);
                    int c = ks * 2 + (lane >> 4);
                    ldsm_x4(ahf[mt], aB + (uint32_t)(rr * 64 + ((c ^ ((rr >> 1) & 3)) << 4)));
                }
                int k = ks * 16 + (lane & 15);
                #pragma unroll
                for (int nt = 0; nt < 4; nt++) {
                    int nl = wn + nt * 16 + ((lane >> 4) << 3);
                    uint32_t boff = (uint32_t)((nl >> 7) * 8192 + k * 256 +
                                               ((((nl & 127) >> 3) ^ (k & 7)) << 4));
                    uint32_t r4[4];
                    ldsm_x4_t(r4, aB + OFF_BH + boff);
                    #pragma unroll
                    for (int mt = 0; mt < 4; mt++) {
                        mma_f16(acc[mt][nt * 2], ahf[mt], r4);
                        mma_f16(acc[mt][nt * 2 + 1], ahf[mt], r4 + 2);
                    }
                }
            }
        };

        issue(0); issue(1); issue(2);
        for (int i = 0; i < nk; i++) {
            asm volatile("cp.async.wait_group 2;" ::: "memory");
            __syncthreads();
            mma_tile(i & (STAGES - 1));
            if (i + 3 < nk) issue(i + 3);
            else asm volatile("cp.async.commit_group;" ::: "memory");
        }
        asm volatile("cp.async.wait_all;" ::: "memory");

        // epilogue: fp16 output
        __half* CH = Ch + (long)bz * strideC;
        #pragma unroll
        for (int mt = 0; mt < 4; mt++) {
            int row0 = m0 + wm + mt * 16 + (lane >> 2);
            #pragma unroll
            for (int n8 = 0; n8 < 8; n8++) {
                int col = n0 + wn + n8 * 8 + (lane & 3) * 2;
                *(__half2*)(CH + (long)row0 * ldc + col) =
                    __floats2half2_rn(acc[mt][n8][0], acc[mt][n8][1]);
                *(__half2*)(CH + (long)(row0 + 8) * ldc + col) =
                    __floats2half2_rn(acc[mt][n8][2], acc[mt][n8][3]);
            }
        }
        if (withStats) {
            int e = g_top1[bz];
            #pragma unroll
            for (int n8 = 0; n8 < 8; n8++) {
                #pragma unroll
                for (int c2 = 0; c2 < 2; c2++) {
                    float s = 0.f, q = 0.f;
                    #pragma unroll
                    for (int mt = 0; mt < 4; mt++) {
                        float v0 = acc[mt][n8][c2], v1 = acc[mt][n8][c2 + 2];
                        s += v0 + v1;
                        q += v0 * v0 + v1 * v1;
                    }
                    s += __shfl_xor_sync(0xFFFFFFFFu, s, 4);
                    q += __shfl_xor_sync(0xFFFFFFFFu, q, 4);
                    s += __shfl_xor_sync(0xFFFFFFFFu, s, 8);
                    q += __shfl_xor_sync(0xFFFFFFFFu, q, 8);
                    s += __shfl_xor_sync(0xFFFFFFFFu, s, 16);
                    q += __shfl_xor_sync(0xFFFFFFFFu, q, 16);
                    if ((lane >> 2) == 0) {
                        int col = n0 + wn + n8 * 8 + (lane & 3) * 2 + c2;
                        atomicAdd(&g_sum[e * H_ + col], s);
                        atomicAdd(&g_ss[e * H_ + col], q);
                    }
                }
            }
        }
        __syncthreads();   // smem reuse barrier before next tile
    }
}

// ---------------- k6: finalize BN scale/shift ----------
__global__ void finalize_kernel(const float* __restrict__ gamma, const float* __restrict__ beta) {
    int e = blockIdx.x, h = threadIdx.x;
    int cg = 0;
    for (int b = 0; b < B_; b++) cg += (g_top1[b] == e);
    float cnt = fmaxf((float)cg * (float)N_, 1.0f);
    float mean = g_sum[e * H_ + h] / cnt;
    float var = g_ss[e * H_ + h] / cnt - mean * mean;
    float inv = rsqrtf(var + BN_EPS);
    float sc = gamma[e * H_ + h] * inv;
    g_scale[e * H_ + h] = sc;
    g_shift[e * H_ + h] = beta[e * H_ + h] - mean * sc;
}

// ---------------- k7: apply BN + ReLU (fp16 in, fp32 out) ----------
__global__ void bn_relu_kernel(float* __restrict__ out) {
    size_t idx = ((size_t)blockIdx.x * blockDim.x + threadIdx.x) * 4;
    int b = (int)(idx / ((size_t)N_ * H_));
    int h = (int)(idx % H_);
    int e = g_top1[b];
    __half2 i0 = *(const __half2*)(g_outh + idx);
    __half2 i1 = *(const __half2*)(g_outh + idx + 2);
    float4 v = make_float4(__half2float(i0.x), __half2float(i0.y),
                           __half2float(i1.x), __half2float(i1.y));
    float4 sc = *(const float4*)&g_scale[e * H_ + h];
    float4 sh = *(const float4*)&g_shift[e * H_ + h];
    v.x = fmaxf(v.x * sc.x + sh.x, 0.f);
    v.y = fmaxf(v.y * sc.y + sh.y, 0.f);
    v.z = fmaxf(v.z * sc.z + sh.z, 0.f);
    v.w = fmaxf(v.w * sc.w + sh.w, 0.f);
    *(float4*)(out + idx) = v;
}

// ---------------- launcher (single stream, serial) ----------------
extern "C" void kernel_launch(void* const* d_in, const int* in_sizes, int n_in,
                              void* d_out, int out_size) {
    (void)in_sizes; (void)n_in; (void)out_size;
    const float* x        = (const float*)d_in[0];   // [B,N,H]
    const float* adj      = (const float*)d_in[1];   // [B,N,N]
    const float* router_w = (const float*)d_in[2];   // [H,E]
    const float* router_b = (const float*)d_in[3];   // [E]
    const float* expert_w = (const float*)d_in[4];   // [E,H,H]
    const float* bn_gamma = (const float*)d_in[5];   // [E,H]
    const float* bn_beta  = (const float*)d_in[6];   // [E,H]
    float* out = (float*)d_out;                      // [B,N,H]

    __half *xh, *adjh, *wh, *suph, *outh;
    cudaGetSymbolAddress((void**)&xh, g_xh);
    cudaGetSymbolAddress((void**)&adjh, g_adjh);
    cudaGetSymbolAddress((void**)&wh, g_wh);
    cudaGetSymbolAddress((void**)&suph, g_suph);
    cudaGetSymbolAddress((void**)&outh, g_outh);

    static int nsm = 0;
    if (!nsm) {
        int dev = 0;
        cudaGetDevice(&dev);
        cudaDeviceGetAttribute(&nsm, cudaDevAttrMultiProcessorCount, dev);
        if (nsm <= 0) nsm = 148;
        cudaFuncSetAttribute(gemm_f16_kernel, cudaFuncAttributeMaxDynamicSharedMemorySize, SMEM_BYTES);
    }

    mean_cvt_kernel<<<dim3(B_, 8), 256>>>(x);
    router_kernel<<<B_, 256>>>(router_w, router_b);
    cvt_adj_kernel<<<(unsigned)((size_t)B_ * N_ * N_ / 4 / 256), 256>>>(adj);
    cvt_w_kernel<<<(unsigned)((size_t)E_ * H_ * H_ / 4 / 256), 256>>>(expert_w);

    const int nTilesN = H_ / BNG;                            // 4
    const int nTilesTotal = nTilesN * (N_ / BM) * B_;        // 1024

    // support[b] = x[b] @ expert_w[top1[b]]  -> fp16  (persistent)
    gemm_f16_kernel<<<nsm, GT, SMEM_BYTES>>>(
        xh, (long)N_ * H_, H_,
        wh, (long)H_ * H_, H_, 1,
        suph, 0, (long)N_ * H_, H_, H_, nTilesN, nTilesTotal);

    // outh[b] = adj[b] @ support[b]  -> fp16 + fused stats  (persistent)
    gemm_f16_kernel<<<nsm, GT, SMEM_BYTES>>>(
        adjh, (long)N_ * N_, N_,
        suph, (long)N_ * H_, H_, 0,
        outh, 1, (long)N_ * H_, H_, N_, nTilesN, nTilesTotal);

    finalize_kernel<<<E_, H_>>>(bn_gamma, bn_beta);

    size_t total4 = (size_t)B_ * N_ * H_ / 4;
    bn_relu_kernel<<<(unsigned)(total4 / 256), 256>>>(out);
}